// round 17
// baseline (speedup 1.0000x reference)
#include <cuda_runtime.h>
#include <math.h>

// Problem constants: B=32, C=3, H=W=512
#define BB 32
#define CC 3
#define HH 512
#define WW 512
#define PX 4

// Fused kernel with per-batch optimal warp-tile aspect a x (32/a), a in {4,8,16,32}.
// a=32 degenerates to the proven row mapping. Choice minimizes a gather-footprint
// cost model; it is uniform per batch, so every branch is warp-uniform.
// Body: warp-uniform dead-segment zero-fill + guarded gathers + streaming stores.
__global__ __launch_bounds__(256, 8) void warp_kernel(const float* __restrict__ x,
                                                      const float* __restrict__ thetas,
                                                      const float* __restrict__ l1s,
                                                      const float* __restrict__ l2s,
                                                      float* __restrict__ out) {
    int lane    = threadIdx.x;                        // 0..31
    int ty      = threadIdx.y;                        // 0..7
    int b       = blockIdx.z;
    int px_base = blockIdx.x * 128;                   // CTA: 128 px in x
    int py_base = blockIdx.y * 8;                     // CTA: 8 rows in y

    // theta matrix (translation exactly zero); uniform within the CTA
    float th = -__ldg(thetas + b);
    float c, s;
    __sincosf(th, &s, &c);
    float il1 = 1.0f / __ldg(l1s + b);
    float il2 = 1.0f / __ldg(l2s + b);
    float m00 = c * c * il1 + s * s * il2;
    float m11 = s * s * il1 + c * c * il2;
    float m01 = c * s * (il2 - il1);
    float am01 = fabsf(m01);

    // ---- per-batch tile-aspect selection (uniform) ----
    int lg = 5;
    {
        float best = 1e30f;
#pragma unroll
        for (int L = 2; L <= 5; L++) {
            float af = (float)(1 << L);
            float rf = (float)(32 >> L);
            float ys = (af - 1.0f) * am01 + (rf - 1.0f) * m11;
            float xs = (af - 1.0f) * m00 + (rf - 1.0f) * am01;
            float cost = (ys + 1.0f) * (xs * 0.03125f + 1.0f);
            if (cost < best) { best = cost; lg = L; }
        }
    }
    int a  = 1 << lg;          // lanes in x
    int rr = 32 >> lg;         // lanes in y
    int i_l = lane & (a - 1);
    int j_l = lane >> lg;
    int tx_w = ty & ((32 >> lg) - 1);   // tiles_x = 32>>lg
    int ty_w = ty >> (5 - lg);
    int pxw = px_base + tx_w * (a << 2);   // warp tile: (4a) x rr
    int pyw = py_base + ty_w * rr;
    int py  = pyw + j_l;
    int px0 = pxw + i_l;

    const float MARGIN = 1e-3f;

    // ---- warp-uniform dead-region test (4 extreme corners of warp tile) ----
    {
        float Xlo = ((float)pxw + 0.5f)              * (2.0f / WW) - 1.0f;
        float Xhi = ((float)pxw + (float)(a << 2) - 0.5f) * (2.0f / WW) - 1.0f;
        float Ylo = ((float)pyw + 0.5f)              * (2.0f / HH) - 1.0f;
        float Yhi = ((float)pyw + (float)rr - 0.5f)  * (2.0f / HH) - 1.0f;

        float ax_lo = fminf(m01 * Ylo, m01 * Yhi);
        float ax_hi = fmaxf(m01 * Ylo, m01 * Yhi);
        float gx_lo = (m00 * Xlo + ax_lo + 1.0f) * (WW * 0.5f) - 0.5f;
        float gx_hi = (m00 * Xhi + ax_hi + 1.0f) * (WW * 0.5f) - 0.5f;

        float ay_lo = fminf(m01 * Xlo, m01 * Xhi);
        float ay_hi = fmaxf(m01 * Xlo, m01 * Xhi);
        float gy_lo = (m11 * Ylo + ay_lo + 1.0f) * (HH * 0.5f) - 0.5f;
        float gy_hi = (m11 * Yhi + ay_hi + 1.0f) * (HH * 0.5f) - 0.5f;

        bool dead = (gx_hi < -1.0f - MARGIN) | (gx_lo >= (float)WW + MARGIN) |
                    (gy_hi < -1.0f - MARGIN) | (gy_lo >= (float)HH + MARGIN);
        if (dead) {   // zero-fill warp tile: a float4-slots per row, rr rows
            float4 z = make_float4(0.f, 0.f, 0.f, 0.f);
            int sz = lane & (a - 1);       // float4 slot within row
            int rz = lane >> lg;           // row within tile
            float4* dst = (float4*)(out + ((size_t)b * CC) * HH * WW +
                                    (size_t)(pyw + rz) * WW + pxw) + sz;
#pragma unroll
            for (int cc = 0; cc < CC; cc++)
                __stcs(dst + cc * (HH * WW / 4), z);
            return;
        }
    }

    float X  = ((float)px0 + 0.5f) * (2.0f / (float)WW) - 1.0f;
    float Y  = ((float)py  + 0.5f) * (2.0f / (float)HH) - 1.0f;
    float gx = (m00 * X + m01 * Y + 1.0f) * ((float)WW * 0.5f) - 0.5f;
    float gy = (m01 * X + m11 * Y + 1.0f) * ((float)HH * 0.5f) - 0.5f;
    float af = (float)a;
    float sx = af * m00;
    float sy = af * m01;

    float w00[PX], w01[PX], w10[PX], w11[PX];
    int   i00[PX];

#pragma unroll
    for (int k = 0; k < PX; k++) {
        float x0f = floorf(gx), y0f = floorf(gy);
        int x0 = (int)x0f, y0 = (int)y0f;
        float wx1 = gx - x0f, wx0 = 1.0f - wx1;
        float wy1 = gy - y0f, wy0 = 1.0f - wy1;
        float cx0 = ((unsigned)x0       < (unsigned)WW) ? wx0 : 0.0f;
        float cx1 = ((unsigned)(x0 + 1) < (unsigned)WW) ? wx1 : 0.0f;
        float cy0 = ((unsigned)y0       < (unsigned)HH) ? wy0 : 0.0f;
        float cy1 = ((unsigned)(y0 + 1) < (unsigned)HH) ? wy1 : 0.0f;
        w00[k] = cy0 * cx0;  w01[k] = cy0 * cx1;
        w10[k] = cy1 * cx0;  w11[k] = cy1 * cx1;
        i00[k] = y0 * WW + x0;
        gx += sx; gy += sy;
    }

    const float* xb = x + (size_t)b * CC * HH * WW;
    float* ob = out + ((size_t)b * CC) * HH * WW + (size_t)py * WW + px0;

#pragma unroll
    for (int cc = 0; cc < CC; cc++) {
        const float* p = xb + (size_t)cc * HH * WW;
        float v[PX];
#pragma unroll
        for (int k = 0; k < PX; k++) {
            int i0 = i00[k];
            float acc = 0.0f;
            if (w00[k] != 0.0f) acc += w00[k] * __ldg(p + i0);
            if (w01[k] != 0.0f) acc += w01[k] * __ldg(p + i0 + 1);
            if (w10[k] != 0.0f) acc += w10[k] * __ldg(p + i0 + WW);
            if (w11[k] != 0.0f) acc += w11[k] * __ldg(p + i0 + WW + 1);
            v[k] = acc;
        }
        float* oc = ob + (size_t)cc * HH * WW;
#pragma unroll
        for (int k = 0; k < PX; k++)
            __stcs(oc + a * k, v[k]);
    }
}

extern "C" void kernel_launch(void* const* d_in, const int* in_sizes, int n_in,
                              void* d_out, int out_size) {
    const float* x      = (const float*)d_in[0];
    const float* thetas = (const float*)d_in[1];
    const float* l1s    = (const float*)d_in[2];
    const float* l2s    = (const float*)d_in[3];
    float* out = (float*)d_out;

    dim3 block(32, 8, 1);
    dim3 grid(4, 64, BB);   // 128 px x 8 rows per CTA = 8192 CTAs
    warp_kernel<<<grid, block>>>(x, thetas, l1s, l2s, out);
}